// round 7
// baseline (speedup 1.0000x reference)
#include <cuda_runtime.h>

// CGMMTransition: N=10000, L=5, A=6, C=20, C2=20
// Persistent work-stealing kernel with double-buffered stats prefetch.
// Outputs (concatenated in d_out, fp32):
//   p_Q_given_obs        [N, C]           at offset 0
//   transition_posterior [N, L, A, C, C2] at offset N*C
//   rightmost_term       [N, L, A, C, C2] at offset N*C + N*L*A*C*C2

#define LVAL   5
#define AVAL   6
#define CVAL   20
#define C2VAL  20
#define LA     30      // L*A
#define KDIM   600     // LA*C2
#define PER_N  12000   // LA*C*C2
#define PER_N4 3000    // PER_N/4
#define NTHREADS 256
#define NWARPS 8
#define NITER  12      // ceil(3000/256); iter 11 partial (tid < 184)
#define TAIL   (PER_N4 - 11 * NTHREADS)   // 184
#define GRID   912     // persistent CTAs (152 SMs x 6)

__device__ int g_ctr;

__global__ void reset_ctr_kernel() { g_ctr = GRID; }

__global__ void __launch_bounds__(NTHREADS, 6)
cgmm_kernel(const float* __restrict__ stats,
            const float* __restrict__ layerS,
            const float* __restrict__ arcS,
            const float* __restrict__ T,
            float* __restrict__ out_pq,
            float* __restrict__ out_tp,
            float* __restrict__ out_rt,
            int N)
{
    __shared__ float s_stats[2][KDIM];
    __shared__ float s_inv[2][LA];
    __shared__ float s_w[LA];
    __shared__ float s_pqw[NWARPS][CVAL];   // per-warp c-bins (non-atomic)
    __shared__ int   s_nn;

    const int tid  = threadIdx.x;
    const int warp = tid >> 5;
    const int lane = tid & 31;

    // ---- one-time setup ----
    if (tid < LA) s_w[tid] = layerS[tid / AVAL] * arcS[tid];
    if (tid < NWARPS * CVAL) reinterpret_cast<float*>(s_pqw)[tid] = 0.0f;

    int n = blockIdx.x;                     // first n: static (no atomic)
    float4 rbuf;
    if (tid < KDIM / 4)
        rbuf = __ldcs(&reinterpret_cast<const float4*>(
                          stats + (size_t)n * KDIM)[tid]);
    if (tid == 0) s_nn = atomicAdd(&g_ctr, 1);
    if (tid < KDIM / 4)
        reinterpret_cast<float4*>(s_stats[0])[tid] = rbuf;
    __syncthreads();

    int b = 0;
    if (tid < LA) {
        float s = 0.0f;
        #pragma unroll
        for (int j = 0; j < C2VAL; ++j) s += s_stats[b][tid * C2VAL + j];
        s_inv[b][tid] = (s == 0.0f) ? 1.0f : 1.0f / s;
    }
    __syncthreads();

    while (n < N) {
        // n_next was published before the last barrier -> uniform & race-free
        const int n_next = s_nn;
        if (n_next < N && tid < KDIM / 4)
            rbuf = __ldcs(&reinterpret_cast<const float4*>(
                              stats + (size_t)n_next * KDIM)[tid]);

        // ---- main elementwise stream for n ----
        const size_t base = (size_t)n * PER_N;   // 48000 B -> 16B aligned
        const float4* T4  = reinterpret_cast<const float4*>(T);
        float4* rt4 = reinterpret_cast<float4*>(out_rt + base);
        float4* tp4 = reinterpret_cast<float4*>(out_tp + base);

        // division-free index state for i = tid + 256*k (element e = 4*i)
        int m    = tid % 5;                 // c2 block = 4*m
        int c    = (tid / 5) % CVAL;
        int la   = tid / 100;
        int r100 = tid % 100;

        #pragma unroll
        for (int k = 0; k < NITER; ++k) {
            const int  i   = tid + k * NTHREADS;
            const bool act = (k < NITER - 1) || (tid < TAIL);

            float v = 0.0f;
            if (act) {
                const float4 t  = __ldg(&T4[i]);   // L1-resident, coalesced
                const float4 sv = *reinterpret_cast<const float4*>(
                                      s_stats[b] + la * C2VAL + 4 * m);
                const float inv = s_inv[b][la];
                const float w   = s_w[la];
                float4 r, p;
                r.x = t.x * sv.x * inv;  r.y = t.y * sv.y * inv;
                r.z = t.z * sv.z * inv;  r.w = t.w * sv.w * inv;
                p.x = r.x * w;  p.y = r.y * w;  p.z = r.z * w;  p.w = r.w * w;
                __stcs(&rt4[i], r);   // streaming stores
                __stcs(&tp4[i], p);
                v = (p.x + p.y) + (p.z + p.w);
            }

            // segmented reduction over runs of 5 equal-c lanes (d = 1,2,4)
            float o;
            o = __shfl_down_sync(0xFFFFFFFFu, v, 1);
            if (m <= 3 && lane < 31) v += o;
            o = __shfl_down_sync(0xFFFFFFFFu, v, 2);
            if (m <= 2 && lane < 30) v += o;
            o = __shfl_down_sync(0xFFFFFFFFu, v, 4);
            if (m == 0 && lane < 28) v += o;

            // head lanes have distinct c within a warp-iter -> plain RMW safe
            if (m == 0 || lane == 0) s_pqw[warp][c] += v;

            const bool wrap = (m == 4);
            m = wrap ? 0 : m + 1;
            c += wrap ? 12 : 11;
            if (c >= CVAL) c -= CVAL;
            la += 2; r100 += 56;
            if (r100 >= 100) { la += 1; r100 -= 100; }
        }

        __syncthreads();   // A: stream + pqw bins complete; prev buffer free

        // p_Q readout for n; zero bins for the next n
        if (tid < CVAL) {
            float s = 0.0f;
            #pragma unroll
            for (int w8 = 0; w8 < NWARPS; ++w8) {
                s += s_pqw[w8][tid];
                s_pqw[w8][tid] = 0.0f;
            }
            out_pq[(size_t)n * CVAL + tid] = s;
        }
        // stage prefetched stats into the other bank
        if (n_next < N && tid < KDIM / 4)
            reinterpret_cast<float4*>(s_stats[b ^ 1])[tid] = rbuf;
        // order the n after next (consumed at next loop top, after barrier C)
        if (tid == 0) s_nn = atomicAdd(&g_ctr, 1);

        __syncthreads();   // B: staged stats + zeroed bins + s_nn visible

        n = n_next;
        b ^= 1;
        if (n < N && tid < LA) {
            float s = 0.0f;
            #pragma unroll
            for (int j = 0; j < C2VAL; ++j) s += s_stats[b][tid * C2VAL + j];
            s_inv[b][tid] = (s == 0.0f) ? 1.0f : 1.0f / s;
        }
        __syncthreads();   // C: inv visible
    }
}

extern "C" void kernel_launch(void* const* d_in, const int* in_sizes, int n_in,
                              void* d_out, int out_size)
{
    const float* stats  = (const float*)d_in[0];  // [N, L, A, C2]
    const float* layerS = (const float*)d_in[1];  // [L]
    const float* arcS   = (const float*)d_in[2];  // [L, A]
    const float* T      = (const float*)d_in[3];  // [L, A, C, C2]

    const int N = in_sizes[0] / KDIM;

    float* out    = (float*)d_out;
    float* out_pq = out;
    float* out_tp = out_pq + (size_t)N * CVAL;
    float* out_rt = out_tp + (size_t)N * PER_N;

    reset_ctr_kernel<<<1, 1>>>();
    cgmm_kernel<<<GRID, NTHREADS>>>(stats, layerS, arcS, T,
                                    out_pq, out_tp, out_rt, N);
}